// round 8
// baseline (speedup 1.0000x reference)
#include <cuda_runtime.h>
#include <cuda_bf16.h>
#include <math.h>
#include <stdint.h>

// ---------------- problem constants ----------------
#define TT    16384
#define CC    512
#define C3    1536
#define HID   2048
#define NHEAD 8
#define HDIM  64
#define SEQ   256
#define NSEQ  64

typedef unsigned long long u64;

// ---------------- scratch ----------------
__device__ float g_h1 [(size_t)TT * CC];
__device__ float g_qkv[(size_t)TT * C3];
__device__ float g_o  [(size_t)TT * CC];
__device__ float g_x1 [(size_t)TT * CC];
__device__ float g_h2 [(size_t)TT * CC];
__device__ float g_ff [(size_t)TT * HID];

// ---------------- f32x2 helpers (attention) ----------------
static __device__ __forceinline__ u64 pack2(float lo, float hi) {
    u64 r; asm("mov.b64 %0,{%1,%2};" : "=l"(r) : "f"(lo), "f"(hi)); return r;
}
static __device__ __forceinline__ float2 unpack2(u64 v) {
    float2 r; asm("mov.b64 {%0,%1},%2;" : "=f"(r.x), "=f"(r.y) : "l"(v)); return r;
}
static __device__ __forceinline__ u64 fma2(u64 a, u64 b, u64 c) {
    u64 d; asm("fma.rn.f32x2 %0,%1,%2,%3;" : "=l"(d) : "l"(a), "l"(b), "l"(c)); return d;
}
static __device__ __forceinline__ u64 mul2(u64 a, u64 b) {
    u64 d; asm("mul.rn.f32x2 %0,%1,%2;" : "=l"(d) : "l"(a), "l"(b)); return d;
}

// ---------------- mma.sync / ldmatrix helpers (sm_80+ PTX) ----------------
static __device__ __forceinline__ uint32_t smem_u32(const void* p) {
    uint32_t a;
    asm("{ .reg .u64 t; cvta.to.shared.u64 t, %1; cvt.u32.u64 %0, t; }" : "=r"(a) : "l"(p));
    return a;
}
static __device__ __forceinline__ void ldmat_x4(uint32_t* r, uint32_t addr) {
    asm volatile("ldmatrix.sync.aligned.m8n8.x4.shared.b16 {%0,%1,%2,%3}, [%4];"
        : "=r"(r[0]), "=r"(r[1]), "=r"(r[2]), "=r"(r[3]) : "r"(addr));
}
static __device__ __forceinline__ void ldmat_x2(uint32_t* r, uint32_t addr) {
    asm volatile("ldmatrix.sync.aligned.m8n8.x2.shared.b16 {%0,%1}, [%2];"
        : "=r"(r[0]), "=r"(r[1]) : "r"(addr));
}
static __device__ __forceinline__ void mma_bf16(float* d, const uint32_t* a, const uint32_t* b) {
    asm volatile("mma.sync.aligned.m16n8k16.row.col.f32.bf16.bf16.f32 "
        "{%0,%1,%2,%3},{%4,%5,%6,%7},{%8,%9},{%0,%1,%2,%3};"
        : "+f"(d[0]), "+f"(d[1]), "+f"(d[2]), "+f"(d[3])
        : "r"(a[0]), "r"(a[1]), "r"(a[2]), "r"(a[3]), "r"(b[0]), "r"(b[1]));
}

// ---------------- bf16-split tensor GEMM (NT): C = A[M,K] * B[N,K]^T --------
// 3-term split: A=Ahi+Alo, B=Bhi+Blo (bf16); D += AhiBhi + AhiBlo + AloBhi.
// Block tile 128x128, 8 warps of 64x32, K chunk 64, double-buffered smem.
// MMA terms are issued TERM-MAJOR so same-accumulator HMMAs are 15 apart.
#define KCH    64
#define ASTR   144                       // bytes per smem row (64 bf16 + 8 pad)
#define TILE_B (128 * ASTR)              // 18432 B, one hi or lo tile
#define BUF_B  (4 * TILE_B)              // Ahi, Alo, Bhi, Blo = 73728 B
#define GEMM_SMEM (2 * BUF_B)            // 147456 B

static __device__ __forceinline__ void cvt_split_store(float4 v, char* hi_t, char* lo_t,
                                                       int row, int c4) {
    uint32_t off = (uint32_t)row * ASTR + (uint32_t)c4 * 2u;
    uint32_t h01, h23, l01, l23;
    asm("cvt.rn.bf16x2.f32 %0, %1, %2;" : "=r"(h01) : "f"(v.y), "f"(v.x));
    asm("cvt.rn.bf16x2.f32 %0, %1, %2;" : "=r"(h23) : "f"(v.w), "f"(v.z));
    float hx = __uint_as_float(h01 << 16);
    float hy = __uint_as_float(h01 & 0xFFFF0000u);
    float hz = __uint_as_float(h23 << 16);
    float hw = __uint_as_float(h23 & 0xFFFF0000u);
    asm("cvt.rn.bf16x2.f32 %0, %1, %2;" : "=r"(l01) : "f"(v.y - hy), "f"(v.x - hx));
    asm("cvt.rn.bf16x2.f32 %0, %1, %2;" : "=r"(l23) : "f"(v.w - hw), "f"(v.z - hz));
    *(uint2*)(hi_t + off) = make_uint2(h01, h23);
    *(uint2*)(lo_t + off) = make_uint2(l01, l23);
}

// EPI: 0 none; 1 +bias[n]+res[m,n]; 2 gelu(+bias[n]) exact
template <int EPI>
__global__ void __launch_bounds__(256, 1)
gemm_mma(const float* __restrict__ A, const float* __restrict__ B,
         float* __restrict__ Cmat, const float* __restrict__ bias,
         const float* __restrict__ res, int M, int N, int K) {
    extern __shared__ char smem[];
    const uint32_t sb = smem_u32(smem);
    const int tid  = threadIdx.x;
    const int wid  = tid >> 5;
    const int lane = tid & 31;
    const int bm = blockIdx.y << 7;
    const int bn = blockIdx.x << 7;

    const int wm = (wid & 1) * 64;       // warp m-offset in tile
    const int wn = (wid >> 1) * 32;      // warp n-offset in tile

    const uint32_t aro = (uint32_t)(lane & 15) * ASTR + (uint32_t)(lane >> 4) * 16u;
    const uint32_t bro = (uint32_t)(lane & 7) * ASTR + (uint32_t)((lane >> 3) & 1) * 16u;

    float acc[4][4][4];
#pragma unroll
    for (int i = 0; i < 4; i++)
#pragma unroll
        for (int j = 0; j < 4; j++)
#pragma unroll
            for (int e = 0; e < 4; e++) acc[i][j][e] = 0.f;

    const int NC = K / KCH;

    // ---- stage chunk 0 into buffer 0 ----
    {
        char* bp = smem;
#pragma unroll
        for (int i = 0; i < 8; i++) {
            int f = i * 256 + tid;
            int row = f >> 4, c4 = (f & 15) << 2;
            float4 v = *(const float4*)(A + (size_t)(bm + row) * K + c4);
            cvt_split_store(v, bp, bp + TILE_B, row, c4);
        }
#pragma unroll
        for (int i = 0; i < 8; i++) {
            int f = i * 256 + tid;
            int row = f >> 4, c4 = (f & 15) << 2;
            float4 v = *(const float4*)(B + (size_t)(bn + row) * K + c4);
            cvt_split_store(v, bp + 2 * TILE_B, bp + 3 * TILE_B, row, c4);
        }
    }
    __syncthreads();

    for (int c = 0; c < NC; ++c) {
        // ---- prefetch chunk c+1 into other buffer ----
        if (c + 1 < NC) {
            char* bp = smem + ((c + 1) & 1) * BUF_B;
            const int kb = (c + 1) * KCH;
#pragma unroll
            for (int i = 0; i < 8; i++) {
                int f = i * 256 + tid;
                int row = f >> 4, c4 = (f & 15) << 2;
                float4 v = *(const float4*)(A + (size_t)(bm + row) * K + kb + c4);
                cvt_split_store(v, bp, bp + TILE_B, row, c4);
            }
#pragma unroll
            for (int i = 0; i < 8; i++) {
                int f = i * 256 + tid;
                int row = f >> 4, c4 = (f & 15) << 2;
                float4 v = *(const float4*)(B + (size_t)(bn + row) * K + kb + c4);
                cvt_split_store(v, bp + 2 * TILE_B, bp + 3 * TILE_B, row, c4);
            }
        }

        // ---- compute chunk c ----
        const uint32_t bufb = sb + (c & 1) * BUF_B;
        const uint32_t aHi = bufb,              aLo = bufb + TILE_B;
        const uint32_t bHi = bufb + 2 * TILE_B, bLo = bufb + 3 * TILE_B;

#pragma unroll
        for (int ks = 0; ks < 4; ks++) {
            const uint32_t kso = (uint32_t)ks * 32u;
            uint32_t bh[4][2], bl[4][2];
#pragma unroll
            for (int nt = 0; nt < 4; nt++) {
                const uint32_t ro = (uint32_t)(wn + nt * 8) * ASTR + kso + bro;
                ldmat_x2(bh[nt], bHi + ro);
                ldmat_x2(bl[nt], bLo + ro);
            }
            uint32_t ah[4][4], al[4][4];
#pragma unroll
            for (int mt = 0; mt < 4; mt++) {
                const uint32_t ro = (uint32_t)(wm + mt * 16) * ASTR + kso + aro;
                ldmat_x4(ah[mt], aHi + ro);
                ldmat_x4(al[mt], aLo + ro);
            }
            // TERM-MAJOR: 16 independent MMAs between same-acc reuses
#pragma unroll
            for (int mt = 0; mt < 4; mt++)
#pragma unroll
                for (int nt = 0; nt < 4; nt++)
                    mma_bf16(acc[mt][nt], ah[mt], bh[nt]);
#pragma unroll
            for (int mt = 0; mt < 4; mt++)
#pragma unroll
                for (int nt = 0; nt < 4; nt++)
                    mma_bf16(acc[mt][nt], ah[mt], bl[nt]);
#pragma unroll
            for (int mt = 0; mt < 4; mt++)
#pragma unroll
                for (int nt = 0; nt < 4; nt++)
                    mma_bf16(acc[mt][nt], al[mt], bh[nt]);
        }
        __syncthreads();
    }

    // ---- epilogue from register fragments ----
    const int g   = lane >> 2;
    const int tig = lane & 3;
#pragma unroll
    for (int mt = 0; mt < 4; mt++) {
#pragma unroll
        for (int half = 0; half < 2; half++) {
            const int m = bm + wm + mt * 16 + g + 8 * half;
            float* crow = Cmat + (size_t)m * N;
            const float* rrow = (EPI == 1) ? (res + (size_t)m * N) : nullptr;
#pragma unroll
            for (int nt = 0; nt < 4; nt++) {
                const int cb = bn + wn + nt * 8 + 2 * tig;
                float v0 = acc[mt][nt][2 * half];
                float v1 = acc[mt][nt][2 * half + 1];
                if (EPI == 1) {
                    float2 rv = *(const float2*)(rrow + cb);
                    v0 += bias[cb] + rv.x;
                    v1 += bias[cb + 1] + rv.y;
                } else if (EPI == 2) {
                    float t0 = v0 + bias[cb], t1 = v1 + bias[cb + 1];
                    v0 = 0.5f * t0 * (1.0f + erff(t0 * 0.70710678118654752f));
                    v1 = 0.5f * t1 * (1.0f + erff(t1 * 0.70710678118654752f));
                }
                float2 ov = { v0, v1 };
                *(float2*)(crow + cb) = ov;
            }
        }
    }
}

// ---------------- LayerNorm: one warp per token ----------------
__global__ void ln_kernel(const float* __restrict__ x, const float* __restrict__ g,
                          const float* __restrict__ b, float* __restrict__ out) {
    const int warp = (blockIdx.x * 256 + threadIdx.x) >> 5;
    const int lane = threadIdx.x & 31;
    const float4* row = (const float4*)(x + (size_t)warp * CC);
    float4 v[4];
    float s = 0.f, q = 0.f;
#pragma unroll
    for (int i = 0; i < 4; i++) {
        v[i] = row[lane + 32 * i];
        s += v[i].x + v[i].y + v[i].z + v[i].w;
        q += v[i].x * v[i].x + v[i].y * v[i].y + v[i].z * v[i].z + v[i].w * v[i].w;
    }
#pragma unroll
    for (int o = 16; o; o >>= 1) {
        s += __shfl_xor_sync(0xFFFFFFFFu, s, o);
        q += __shfl_xor_sync(0xFFFFFFFFu, q, o);
    }
    const float mu  = s * (1.0f / CC);
    const float var = fmaxf(q * (1.0f / CC) - mu * mu, 0.0f);
    const float r   = rsqrtf(var + 1e-5f);

    float4* orow = (float4*)(out + (size_t)warp * CC);
    const float4* gg = (const float4*)g;
    const float4* bb = (const float4*)b;
#pragma unroll
    for (int i = 0; i < 4; i++) {
        float4 gv = gg[lane + 32 * i], bv = bb[lane + 32 * i], ov;
        ov.x = (v[i].x - mu) * r * gv.x + bv.x;
        ov.y = (v[i].y - mu) * r * gv.y + bv.y;
        ov.z = (v[i].z - mu) * r * gv.z + bv.z;
        ov.w = (v[i].w - mu) * r * gv.w + bv.w;
        orow[lane + 32 * i] = ov;
    }
}

// ---------------- Attention: one block per (seq, head), online softmax ------
__global__ void __launch_bounds__(256, 1)
attn_kernel(const float* __restrict__ qkv, float* __restrict__ o) {
    __shared__ float Ks[64 * 64];
    __shared__ float Vs[64 * 64];
    const int head = blockIdx.x;
    const int seqb = blockIdx.y * SEQ;
    const int tid  = threadIdx.x;
    const int tq   = seqb + tid;

    u64 q2[32], o2[32];
    {
        const float4* qp = (const float4*)(qkv + (size_t)tq * C3 + head * HDIM);
#pragma unroll
        for (int t = 0; t < 16; t++) {
            float4 v = qp[t];
            q2[2 * t]     = pack2(v.x * 0.125f, v.y * 0.125f);
            q2[2 * t + 1] = pack2(v.z * 0.125f, v.w * 0.125f);
            o2[2 * t] = 0ull; o2[2 * t + 1] = 0ull;
        }
    }
    float mx = -1e30f, sm = 0.f;

    for (int ck = 0; ck < 4; ++ck) {
        __syncthreads();
#pragma unroll
        for (int it = 0; it < 4; ++it) {
            const int idx = it * 256 + tid;
            const int r = idx >> 4, c4 = idx & 15;
            const float* base = qkv + (size_t)(seqb + ck * 64 + r) * C3 + head * HDIM + c4 * 4;
            ((float4*)Ks)[idx] = *(const float4*)(base + 512);
            ((float4*)Vs)[idx] = *(const float4*)(base + 1024);
        }
        __syncthreads();

        for (int m = 0; m < 64; m++) {
            const u64* K2 = (const u64*)(Ks + m * 64);
            u64 s4[4] = { 0ull, 0ull, 0ull, 0ull };
#pragma unroll
            for (int j = 0; j < 32; j += 4) {
                s4[0] = fma2(q2[j + 0], K2[j + 0], s4[0]);
                s4[1] = fma2(q2[j + 1], K2[j + 1], s4[1]);
                s4[2] = fma2(q2[j + 2], K2[j + 2], s4[2]);
                s4[3] = fma2(q2[j + 3], K2[j + 3], s4[3]);
            }
            float2 p0 = unpack2(s4[0]), p1 = unpack2(s4[1]);
            float2 p2 = unpack2(s4[2]), p3 = unpack2(s4[3]);
            const float s = ((p0.x + p0.y) + (p1.x + p1.y)) + ((p2.x + p2.y) + (p3.x + p3.y));

            const float mn   = fmaxf(mx, s);
            const float corr = __expf(mx - mn);
            const float p    = __expf(s - mn);
            sm = sm * corr + p;
            mx = mn;

            const u64 cd = pack2(corr, corr);
            const u64 pd = pack2(p, p);
            const u64* V2 = (const u64*)(Vs + m * 64);
#pragma unroll
            for (int j = 0; j < 32; j++)
                o2[j] = fma2(o2[j], cd, mul2(pd, V2[j]));
        }
    }

    const float inv = 1.0f / sm;
    float4* op = (float4*)(o + (size_t)tq * CC + head * HDIM);
#pragma unroll
    for (int t = 0; t < 16; t++) {
        float2 a = unpack2(o2[2 * t]);
        float2 b = unpack2(o2[2 * t + 1]);
        float4 v = { a.x * inv, a.y * inv, b.x * inv, b.y * inv };
        op[t] = v;
    }
}

// ---------------- launcher ----------------
extern "C" void kernel_launch(void* const* d_in, const int* in_sizes, int n_in,
                              void* d_out, int out_size) {
    const float* x     = (const float*)d_in[0];
    const float* ln1g  = (const float*)d_in[1];
    const float* ln1b  = (const float*)d_in[2];
    const float* wqkv  = (const float*)d_in[3];
    const float* wproj = (const float*)d_in[4];
    const float* bproj = (const float*)d_in[5];
    const float* ln2g  = (const float*)d_in[6];
    const float* ln2b  = (const float*)d_in[7];
    const float* w1    = (const float*)d_in[8];
    const float* b1    = (const float*)d_in[9];
    const float* w2    = (const float*)d_in[10];
    const float* b2    = (const float*)d_in[11];
    float* out = (float*)d_out;

    float *h1, *qkv, *o, *x1, *h2, *ff;
    cudaGetSymbolAddress((void**)&h1,  g_h1);
    cudaGetSymbolAddress((void**)&qkv, g_qkv);
    cudaGetSymbolAddress((void**)&o,   g_o);
    cudaGetSymbolAddress((void**)&x1,  g_x1);
    cudaGetSymbolAddress((void**)&h2,  g_h2);
    cudaGetSymbolAddress((void**)&ff,  g_ff);

    cudaFuncSetAttribute(gemm_mma<0>, cudaFuncAttributeMaxDynamicSharedMemorySize, GEMM_SMEM);
    cudaFuncSetAttribute(gemm_mma<1>, cudaFuncAttributeMaxDynamicSharedMemorySize, GEMM_SMEM);
    cudaFuncSetAttribute(gemm_mma<2>, cudaFuncAttributeMaxDynamicSharedMemorySize, GEMM_SMEM);

    // 1) LN1
    ln_kernel<<<TT / 8, 256>>>(x, ln1g, ln1b, h1);
    // 2) QKV = h1 @ w_qkv^T
    gemm_mma<0><<<dim3(C3 / 128, TT / 128), 256, GEMM_SMEM>>>(h1, wqkv, qkv, nullptr, nullptr, TT, C3, CC);
    // 3) attention
    attn_kernel<<<dim3(NHEAD, NSEQ), 256>>>(qkv, o);
    // 4) x1 = x + o @ w_proj^T + b_proj
    gemm_mma<1><<<dim3(CC / 128, TT / 128), 256, GEMM_SMEM>>>(o, wproj, x1, bproj, x, TT, CC, CC);
    // 5) LN2
    ln_kernel<<<TT / 8, 256>>>(x1, ln2g, ln2b, h2);
    // 6) ff = gelu(h2 @ w1^T + b1)
    gemm_mma<2><<<dim3(HID / 128, TT / 128), 256, GEMM_SMEM>>>(h2, w1, ff, b1, nullptr, TT, HID, CC);
    // 7) out = x1 + ff @ w2^T + b2
    gemm_mma<1><<<dim3(CC / 128, TT / 128), 256, GEMM_SMEM>>>(ff, w2, out, b2, x1, TT, CC, HID);
}

// round 9
// speedup vs baseline: 1.0049x; 1.0049x over previous
#include <cuda_runtime.h>
#include <cuda_bf16.h>
#include <math.h>
#include <stdint.h>

// ---------------- problem constants ----------------
#define TT    16384
#define CC    512
#define C3    1536
#define HID   2048
#define NHEAD 8
#define HDIM  64
#define SEQ   256
#define NSEQ  64

typedef unsigned long long u64;

// ---------------- scratch ----------------
__device__ float g_h1 [(size_t)TT * CC];
__device__ float g_qkv[(size_t)TT * C3];
__device__ float g_o  [(size_t)TT * CC];
__device__ float g_x1 [(size_t)TT * CC];
__device__ float g_h2 [(size_t)TT * CC];
__device__ float g_ff [(size_t)TT * HID];

// ---------------- f32x2 helpers (attention) ----------------
static __device__ __forceinline__ u64 pack2(float lo, float hi) {
    u64 r; asm("mov.b64 %0,{%1,%2};" : "=l"(r) : "f"(lo), "f"(hi)); return r;
}
static __device__ __forceinline__ float2 unpack2(u64 v) {
    float2 r; asm("mov.b64 {%0,%1},%2;" : "=f"(r.x), "=f"(r.y) : "l"(v)); return r;
}
static __device__ __forceinline__ u64 fma2(u64 a, u64 b, u64 c) {
    u64 d; asm("fma.rn.f32x2 %0,%1,%2,%3;" : "=l"(d) : "l"(a), "l"(b), "l"(c)); return d;
}
static __device__ __forceinline__ u64 mul2(u64 a, u64 b) {
    u64 d; asm("mul.rn.f32x2 %0,%1,%2;" : "=l"(d) : "l"(a), "l"(b)); return d;
}

// ---------------- mma.sync / ldmatrix helpers (sm_80+ PTX) ----------------
static __device__ __forceinline__ uint32_t smem_u32(const void* p) {
    uint32_t a;
    asm("{ .reg .u64 t; cvta.to.shared.u64 t, %1; cvt.u32.u64 %0, t; }" : "=r"(a) : "l"(p));
    return a;
}
static __device__ __forceinline__ void ldmat_x4(uint32_t* r, uint32_t addr) {
    asm volatile("ldmatrix.sync.aligned.m8n8.x4.shared.b16 {%0,%1,%2,%3}, [%4];"
        : "=r"(r[0]), "=r"(r[1]), "=r"(r[2]), "=r"(r[3]) : "r"(addr));
}
static __device__ __forceinline__ void ldmat_x2(uint32_t* r, uint32_t addr) {
    asm volatile("ldmatrix.sync.aligned.m8n8.x2.shared.b16 {%0,%1}, [%2];"
        : "=r"(r[0]), "=r"(r[1]) : "r"(addr));
}
static __device__ __forceinline__ void mma_bf16(float* d, const uint32_t* a, const uint32_t* b) {
    asm volatile("mma.sync.aligned.m16n8k16.row.col.f32.bf16.bf16.f32 "
        "{%0,%1,%2,%3},{%4,%5,%6,%7},{%8,%9},{%0,%1,%2,%3};"
        : "+f"(d[0]), "+f"(d[1]), "+f"(d[2]), "+f"(d[3])
        : "r"(a[0]), "r"(a[1]), "r"(a[2]), "r"(a[3]), "r"(b[0]), "r"(b[1]));
}

// ---------------- bf16-split tensor GEMM (NT): C = A[M,K] * B[N,K]^T --------
// 3-term split: A=Ahi+Alo, B=Bhi+Blo (bf16); D += AhiBhi + AhiBlo + AloBhi.
// Block tile 128x128, 512 threads / 16 warps (4x4 grid, 32x32 per warp),
// K chunk 64, double-buffered smem.
#define NTHR   512
#define KCH    64
#define ASTR   144                       // bytes per smem row (64 bf16 + 8 pad)
#define TILE_B (128 * ASTR)              // 18432 B per hi/lo tile
#define BUF_B  (4 * TILE_B)              // Ahi, Alo, Bhi, Blo = 73728 B
#define GEMM_SMEM (2 * BUF_B)            // 147456 B

static __device__ __forceinline__ void cvt_split_store(float4 v, char* hi_t, char* lo_t,
                                                       int row, int c4) {
    uint32_t off = (uint32_t)row * ASTR + (uint32_t)c4 * 2u;
    uint32_t h01, h23, l01, l23;
    asm("cvt.rn.bf16x2.f32 %0, %1, %2;" : "=r"(h01) : "f"(v.y), "f"(v.x));
    asm("cvt.rn.bf16x2.f32 %0, %1, %2;" : "=r"(h23) : "f"(v.w), "f"(v.z));
    float hx = __uint_as_float(h01 << 16);
    float hy = __uint_as_float(h01 & 0xFFFF0000u);
    float hz = __uint_as_float(h23 << 16);
    float hw = __uint_as_float(h23 & 0xFFFF0000u);
    asm("cvt.rn.bf16x2.f32 %0, %1, %2;" : "=r"(l01) : "f"(v.y - hy), "f"(v.x - hx));
    asm("cvt.rn.bf16x2.f32 %0, %1, %2;" : "=r"(l23) : "f"(v.w - hw), "f"(v.z - hz));
    *(uint2*)(hi_t + off) = make_uint2(h01, h23);
    *(uint2*)(lo_t + off) = make_uint2(l01, l23);
}

// EPI: 0 none; 1 +bias[n]+res[m,n]; 2 gelu(+bias[n]) exact
template <int EPI>
__global__ void __launch_bounds__(NTHR, 1)
gemm_mma(const float* __restrict__ A, const float* __restrict__ B,
         float* __restrict__ Cmat, const float* __restrict__ bias,
         const float* __restrict__ res, int M, int N, int K) {
    extern __shared__ char smem[];
    const uint32_t sb = smem_u32(smem);
    const int tid  = threadIdx.x;
    const int wid  = tid >> 5;
    const int lane = tid & 31;
    const int bm = blockIdx.y << 7;
    const int bn = blockIdx.x << 7;

    const int wm = (wid & 3) * 32;       // warp m-offset (4 warps down)
    const int wn = (wid >> 2) * 32;      // warp n-offset (4 warps across)

    const uint32_t aro = (uint32_t)(lane & 15) * ASTR + (uint32_t)(lane >> 4) * 16u;
    const uint32_t bro = (uint32_t)(lane & 7) * ASTR + (uint32_t)((lane >> 3) & 1) * 16u;

    float acc[2][4][4];
#pragma unroll
    for (int i = 0; i < 2; i++)
#pragma unroll
        for (int j = 0; j < 4; j++)
#pragma unroll
            for (int e = 0; e < 4; e++) acc[i][j][e] = 0.f;

    const int NC = K / KCH;

    // ---- stage chunk 0 into buffer 0 (A:2048 float4, B:2048 float4) ----
    {
        char* bp = smem;
#pragma unroll
        for (int i = 0; i < 4; i++) {
            int f = i * NTHR + tid;
            int row = f >> 4, c4 = (f & 15) << 2;
            float4 v = *(const float4*)(A + (size_t)(bm + row) * K + c4);
            cvt_split_store(v, bp, bp + TILE_B, row, c4);
        }
#pragma unroll
        for (int i = 0; i < 4; i++) {
            int f = i * NTHR + tid;
            int row = f >> 4, c4 = (f & 15) << 2;
            float4 v = *(const float4*)(B + (size_t)(bn + row) * K + c4);
            cvt_split_store(v, bp + 2 * TILE_B, bp + 3 * TILE_B, row, c4);
        }
    }
    __syncthreads();

    for (int c = 0; c < NC; ++c) {
        // ---- prefetch chunk c+1 into other buffer ----
        if (c + 1 < NC) {
            char* bp = smem + ((c + 1) & 1) * BUF_B;
            const int kb = (c + 1) * KCH;
#pragma unroll
            for (int i = 0; i < 4; i++) {
                int f = i * NTHR + tid;
                int row = f >> 4, c4 = (f & 15) << 2;
                float4 v = *(const float4*)(A + (size_t)(bm + row) * K + kb + c4);
                cvt_split_store(v, bp, bp + TILE_B, row, c4);
            }
#pragma unroll
            for (int i = 0; i < 4; i++) {
                int f = i * NTHR + tid;
                int row = f >> 4, c4 = (f & 15) << 2;
                float4 v = *(const float4*)(B + (size_t)(bn + row) * K + kb + c4);
                cvt_split_store(v, bp + 2 * TILE_B, bp + 3 * TILE_B, row, c4);
            }
        }

        // ---- compute chunk c ----
        const uint32_t bufb = sb + (c & 1) * BUF_B;
        const uint32_t aHi = bufb,              aLo = bufb + TILE_B;
        const uint32_t bHi = bufb + 2 * TILE_B, bLo = bufb + 3 * TILE_B;

#pragma unroll
        for (int ks = 0; ks < 4; ks++) {
            const uint32_t kso = (uint32_t)ks * 32u;
            uint32_t bh[4][2], bl[4][2];
#pragma unroll
            for (int nt = 0; nt < 4; nt++) {
                const uint32_t ro = (uint32_t)(wn + nt * 8) * ASTR + kso + bro;
                ldmat_x2(bh[nt], bHi + ro);
                ldmat_x2(bl[nt], bLo + ro);
            }
            uint32_t ah[2][4], al[2][4];
#pragma unroll
            for (int mt = 0; mt < 2; mt++) {
                const uint32_t ro = (uint32_t)(wm + mt * 16) * ASTR + kso + aro;
                ldmat_x4(ah[mt], aHi + ro);
                ldmat_x4(al[mt], aLo + ro);
            }
#pragma unroll
            for (int mt = 0; mt < 2; mt++)
#pragma unroll
                for (int nt = 0; nt < 4; nt++) {
                    mma_bf16(acc[mt][nt], ah[mt], bh[nt]);
                    mma_bf16(acc[mt][nt], ah[mt], bl[nt]);
                    mma_bf16(acc[mt][nt], al[mt], bh[nt]);
                }
        }
        __syncthreads();
    }

    // ---- epilogue from register fragments ----
    const int g   = lane >> 2;
    const int tig = lane & 3;
#pragma unroll
    for (int mt = 0; mt < 2; mt++) {
#pragma unroll
        for (int half = 0; half < 2; half++) {
            const int m = bm + wm + mt * 16 + g + 8 * half;
            float* crow = Cmat + (size_t)m * N;
            const float* rrow = (EPI == 1) ? (res + (size_t)m * N) : nullptr;
#pragma unroll
            for (int nt = 0; nt < 4; nt++) {
                const int cb = bn + wn + nt * 8 + 2 * tig;
                float v0 = acc[mt][nt][2 * half];
                float v1 = acc[mt][nt][2 * half + 1];
                if (EPI == 1) {
                    float2 rv = *(const float2*)(rrow + cb);
                    v0 += bias[cb] + rv.x;
                    v1 += bias[cb + 1] + rv.y;
                } else if (EPI == 2) {
                    float t0 = v0 + bias[cb], t1 = v1 + bias[cb + 1];
                    v0 = 0.5f * t0 * (1.0f + erff(t0 * 0.70710678118654752f));
                    v1 = 0.5f * t1 * (1.0f + erff(t1 * 0.70710678118654752f));
                }
                float2 ov = { v0, v1 };
                *(float2*)(crow + cb) = ov;
            }
        }
    }
}

// ---------------- LayerNorm: one warp per token ----------------
__global__ void ln_kernel(const float* __restrict__ x, const float* __restrict__ g,
                          const float* __restrict__ b, float* __restrict__ out) {
    const int warp = (blockIdx.x * 256 + threadIdx.x) >> 5;
    const int lane = threadIdx.x & 31;
    const float4* row = (const float4*)(x + (size_t)warp * CC);
    float4 v[4];
    float s = 0.f, q = 0.f;
#pragma unroll
    for (int i = 0; i < 4; i++) {
        v[i] = row[lane + 32 * i];
        s += v[i].x + v[i].y + v[i].z + v[i].w;
        q += v[i].x * v[i].x + v[i].y * v[i].y + v[i].z * v[i].z + v[i].w * v[i].w;
    }
#pragma unroll
    for (int o = 16; o; o >>= 1) {
        s += __shfl_xor_sync(0xFFFFFFFFu, s, o);
        q += __shfl_xor_sync(0xFFFFFFFFu, q, o);
    }
    const float mu  = s * (1.0f / CC);
    const float var = fmaxf(q * (1.0f / CC) - mu * mu, 0.0f);
    const float r   = rsqrtf(var + 1e-5f);

    float4* orow = (float4*)(out + (size_t)warp * CC);
    const float4* gg = (const float4*)g;
    const float4* bb = (const float4*)b;
#pragma unroll
    for (int i = 0; i < 4; i++) {
        float4 gv = gg[lane + 32 * i], bv = bb[lane + 32 * i], ov;
        ov.x = (v[i].x - mu) * r * gv.x + bv.x;
        ov.y = (v[i].y - mu) * r * gv.y + bv.y;
        ov.z = (v[i].z - mu) * r * gv.z + bv.z;
        ov.w = (v[i].w - mu) * r * gv.w + bv.w;
        orow[lane + 32 * i] = ov;
    }
}

// ---------------- Attention: one block per (seq, head), online softmax ------
__global__ void __launch_bounds__(256, 1)
attn_kernel(const float* __restrict__ qkv, float* __restrict__ o) {
    __shared__ float Ks[64 * 64];
    __shared__ float Vs[64 * 64];
    const int head = blockIdx.x;
    const int seqb = blockIdx.y * SEQ;
    const int tid  = threadIdx.x;
    const int tq   = seqb + tid;

    u64 q2[32], o2[32];
    {
        const float4* qp = (const float4*)(qkv + (size_t)tq * C3 + head * HDIM);
#pragma unroll
        for (int t = 0; t < 16; t++) {
            float4 v = qp[t];
            q2[2 * t]     = pack2(v.x * 0.125f, v.y * 0.125f);
            q2[2 * t + 1] = pack2(v.z * 0.125f, v.w * 0.125f);
            o2[2 * t] = 0ull; o2[2 * t + 1] = 0ull;
        }
    }
    float mx = -1e30f, sm = 0.f;

    for (int ck = 0; ck < 4; ++ck) {
        __syncthreads();
#pragma unroll
        for (int it = 0; it < 4; ++it) {
            const int idx = it * 256 + tid;
            const int r = idx >> 4, c4 = idx & 15;
            const float* base = qkv + (size_t)(seqb + ck * 64 + r) * C3 + head * HDIM + c4 * 4;
            ((float4*)Ks)[idx] = *(const float4*)(base + 512);
            ((float4*)Vs)[idx] = *(const float4*)(base + 1024);
        }
        __syncthreads();

        for (int m = 0; m < 64; m++) {
            const u64* K2 = (const u64*)(Ks + m * 64);
            u64 s4[4] = { 0ull, 0ull, 0ull, 0ull };
#pragma unroll
            for (int j = 0; j < 32; j += 4) {
                s4[0] = fma2(q2[j + 0], K2[j + 0], s4[0]);
                s4[1] = fma2(q2[j + 1], K2[j + 1], s4[1]);
                s4[2] = fma2(q2[j + 2], K2[j + 2], s4[2]);
                s4[3] = fma2(q2[j + 3], K2[j + 3], s4[3]);
            }
            float2 p0 = unpack2(s4[0]), p1 = unpack2(s4[1]);
            float2 p2 = unpack2(s4[2]), p3 = unpack2(s4[3]);
            const float s = ((p0.x + p0.y) + (p1.x + p1.y)) + ((p2.x + p2.y) + (p3.x + p3.y));

            const float mn   = fmaxf(mx, s);
            const float corr = __expf(mx - mn);
            const float p    = __expf(s - mn);
            sm = sm * corr + p;
            mx = mn;

            const u64 cd = pack2(corr, corr);
            const u64 pd = pack2(p, p);
            const u64* V2 = (const u64*)(Vs + m * 64);
#pragma unroll
            for (int j = 0; j < 32; j++)
                o2[j] = fma2(o2[j], cd, mul2(pd, V2[j]));
        }
    }

    const float inv = 1.0f / sm;
    float4* op = (float4*)(o + (size_t)tq * CC + head * HDIM);
#pragma unroll
    for (int t = 0; t < 16; t++) {
        float2 a = unpack2(o2[2 * t]);
        float2 b = unpack2(o2[2 * t + 1]);
        float4 v = { a.x * inv, a.y * inv, b.x * inv, b.y * inv };
        op[t] = v;
    }
}

// ---------------- launcher ----------------
extern "C" void kernel_launch(void* const* d_in, const int* in_sizes, int n_in,
                              void* d_out, int out_size) {
    const float* x     = (const float*)d_in[0];
    const float* ln1g  = (const float*)d_in[1];
    const float* ln1b  = (const float*)d_in[2];
    const float* wqkv  = (const float*)d_in[3];
    const float* wproj = (const float*)d_in[4];
    const float* bproj = (const float*)d_in[5];
    const float* ln2g  = (const float*)d_in[6];
    const float* ln2b  = (const float*)d_in[7];
    const float* w1    = (const float*)d_in[8];
    const float* b1    = (const float*)d_in[9];
    const float* w2    = (const float*)d_in[10];
    const float* b2    = (const float*)d_in[11];
    float* out = (float*)d_out;

    float *h1, *qkv, *o, *x1, *h2, *ff;
    cudaGetSymbolAddress((void**)&h1,  g_h1);
    cudaGetSymbolAddress((void**)&qkv, g_qkv);
    cudaGetSymbolAddress((void**)&o,   g_o);
    cudaGetSymbolAddress((void**)&x1,  g_x1);
    cudaGetSymbolAddress((void**)&h2,  g_h2);
    cudaGetSymbolAddress((void**)&ff,  g_ff);

    cudaFuncSetAttribute(gemm_mma<0>, cudaFuncAttributeMaxDynamicSharedMemorySize, GEMM_SMEM);
    cudaFuncSetAttribute(gemm_mma<1>, cudaFuncAttributeMaxDynamicSharedMemorySize, GEMM_SMEM);
    cudaFuncSetAttribute(gemm_mma<2>, cudaFuncAttributeMaxDynamicSharedMemorySize, GEMM_SMEM);

    // 1) LN1
    ln_kernel<<<TT / 8, 256>>>(x, ln1g, ln1b, h1);
    // 2) QKV = h1 @ w_qkv^T
    gemm_mma<0><<<dim3(C3 / 128, TT / 128), NTHR, GEMM_SMEM>>>(h1, wqkv, qkv, nullptr, nullptr, TT, C3, CC);
    // 3) attention
    attn_kernel<<<dim3(NHEAD, NSEQ), 256>>>(qkv, o);
    // 4) x1 = x + o @ w_proj^T + b_proj
    gemm_mma<1><<<dim3(CC / 128, TT / 128), NTHR, GEMM_SMEM>>>(o, wproj, x1, bproj, x, TT, CC, CC);
    // 5) LN2
    ln_kernel<<<TT / 8, 256>>>(x1, ln2g, ln2b, h2);
    // 6) ff = gelu(h2 @ w1^T + b1)
    gemm_mma<2><<<dim3(HID / 128, TT / 128), NTHR, GEMM_SMEM>>>(h2, w1, ff, b1, nullptr, TT, HID, CC);
    // 7) out = x1 + ff @ w2^T + b2
    gemm_mma<1><<<dim3(CC / 128, TT / 128), NTHR, GEMM_SMEM>>>(ff, w2, out, b2, x1, TT, CC, HID);
}

// round 11
// speedup vs baseline: 1.1543x; 1.1487x over previous
#include <cuda_runtime.h>
#include <cuda_fp16.h>
#include <math.h>
#include <stdint.h>

// ---------------- problem constants ----------------
#define TT    16384
#define CC    512
#define C3    1536
#define HID   2048
#define NHEAD 8
#define HDIM  64
#define SEQ   256
#define NSEQ  64

typedef unsigned long long u64;

// ---------------- scratch ----------------
__device__ float g_h1 [(size_t)TT * CC];
__device__ float g_qkv[(size_t)TT * C3];
__device__ float g_o  [(size_t)TT * CC];
__device__ float g_x1 [(size_t)TT * CC];
__device__ float g_h2 [(size_t)TT * CC];
__device__ float g_ff [(size_t)TT * HID];

// ---------------- f32x2 helpers (attention) ----------------
static __device__ __forceinline__ u64 pack2(float lo, float hi) {
    u64 r; asm("mov.b64 %0,{%1,%2};" : "=l"(r) : "f"(lo), "f"(hi)); return r;
}
static __device__ __forceinline__ float2 unpack2(u64 v) {
    float2 r; asm("mov.b64 {%0,%1},%2;" : "=f"(r.x), "=f"(r.y) : "l"(v)); return r;
}
static __device__ __forceinline__ u64 fma2(u64 a, u64 b, u64 c) {
    u64 d; asm("fma.rn.f32x2 %0,%1,%2,%3;" : "=l"(d) : "l"(a), "l"(b), "l"(c)); return d;
}
static __device__ __forceinline__ u64 mul2(u64 a, u64 b) {
    u64 d; asm("mul.rn.f32x2 %0,%1,%2;" : "=l"(d) : "l"(a), "l"(b)); return d;
}

// ---------------- mma.sync / ldmatrix helpers (sm_80+ PTX) ----------------
static __device__ __forceinline__ uint32_t smem_u32(const void* p) {
    uint32_t a;
    asm("{ .reg .u64 t; cvta.to.shared.u64 t, %1; cvt.u32.u64 %0, t; }" : "=r"(a) : "l"(p));
    return a;
}
static __device__ __forceinline__ void ldmat_x4(uint32_t* r, uint32_t addr) {
    asm volatile("ldmatrix.sync.aligned.m8n8.x4.shared.b16 {%0,%1,%2,%3}, [%4];"
        : "=r"(r[0]), "=r"(r[1]), "=r"(r[2]), "=r"(r[3]) : "r"(addr));
}
static __device__ __forceinline__ void ldmat_x2(uint32_t* r, uint32_t addr) {
    asm volatile("ldmatrix.sync.aligned.m8n8.x2.shared.b16 {%0,%1}, [%2];"
        : "=r"(r[0]), "=r"(r[1]) : "r"(addr));
}
static __device__ __forceinline__ void mma_f16(float* d, const uint32_t* a, const uint32_t* b) {
    asm volatile("mma.sync.aligned.m16n8k16.row.col.f32.f16.f16.f32 "
        "{%0,%1,%2,%3},{%4,%5,%6,%7},{%8,%9},{%0,%1,%2,%3};"
        : "+f"(d[0]), "+f"(d[1]), "+f"(d[2]), "+f"(d[3])
        : "r"(a[0]), "r"(a[1]), "r"(a[2]), "r"(a[3]), "r"(b[0]), "r"(b[1]));
}

// bit-cast __half2 -> uint32_t (no such intrinsic exists; do it manually)
static __device__ __forceinline__ uint32_t h2_u32(__half2 h) {
    union { __half2 h; uint32_t u; } c;
    c.h = h;
    return c.u;
}

// ---------------- fp16 2-term split GEMM (NT): C = A[M,K] * B[N,K]^T --------
// A = Ahi + Alo (fp16 pair, ~2^-24 accurate); B = rn_fp16(B) (~2^-12).
// D = Ahi*Bhi + Alo*Bhi : 2 MMA terms (vs 3 with bf16 split).
// Block tile 128x128, 512 threads / 16 warps (4x4 grid, 32x32 per warp),
// K chunk 64, double-buffered smem.
#define NTHR   512
#define KCH    64
#define ASTR   144                       // bytes per smem row (64 f16 + 8 pad)
#define TILE_B (128 * ASTR)              // 18432 B per tile
#define BUF_B  (3 * TILE_B)              // Ahi, Alo, Bhi = 55296 B
#define GEMM_SMEM (2 * BUF_B)            // 110592 B

// split fp32 float4 -> fp16 hi + lo, store at (row, c4..c4+3)
static __device__ __forceinline__ void cvt_split_storeA(float4 v, char* hi_t, char* lo_t,
                                                        int row, int c4) {
    uint32_t off = (uint32_t)row * ASTR + (uint32_t)c4 * 2u;
    __half2 h01 = __floats2half2_rn(v.x, v.y);
    __half2 h23 = __floats2half2_rn(v.z, v.w);
    float2 f01 = __half22float2(h01);
    float2 f23 = __half22float2(h23);
    __half2 l01 = __floats2half2_rn(v.x - f01.x, v.y - f01.y);
    __half2 l23 = __floats2half2_rn(v.z - f23.x, v.w - f23.y);
    *(uint2*)(hi_t + off) = make_uint2(h2_u32(h01), h2_u32(h23));
    *(uint2*)(lo_t + off) = make_uint2(h2_u32(l01), h2_u32(l23));
}
static __device__ __forceinline__ void cvt_storeB(float4 v, char* hi_t, int row, int c4) {
    uint32_t off = (uint32_t)row * ASTR + (uint32_t)c4 * 2u;
    __half2 h01 = __floats2half2_rn(v.x, v.y);
    __half2 h23 = __floats2half2_rn(v.z, v.w);
    *(uint2*)(hi_t + off) = make_uint2(h2_u32(h01), h2_u32(h23));
}

// EPI: 0 none; 1 +bias[n]+res[m,n]; 2 gelu(+bias[n]) exact
template <int EPI>
__global__ void __launch_bounds__(NTHR, 1)
gemm_mma(const float* __restrict__ A, const float* __restrict__ B,
         float* __restrict__ Cmat, const float* __restrict__ bias,
         const float* __restrict__ res, int M, int N, int K) {
    extern __shared__ char smem[];
    const uint32_t sb = smem_u32(smem);
    const int tid  = threadIdx.x;
    const int wid  = tid >> 5;
    const int lane = tid & 31;
    const int bm = blockIdx.y << 7;
    const int bn = blockIdx.x << 7;

    const int wm = (wid & 3) * 32;       // warp m-offset
    const int wn = (wid >> 2) * 32;      // warp n-offset

    const uint32_t aro = (uint32_t)(lane & 15) * ASTR + (uint32_t)(lane >> 4) * 16u;
    const uint32_t bro = (uint32_t)(lane & 7) * ASTR + (uint32_t)((lane >> 3) & 1) * 16u;

    float acc[2][4][4];
#pragma unroll
    for (int i = 0; i < 2; i++)
#pragma unroll
        for (int j = 0; j < 4; j++)
#pragma unroll
            for (int e = 0; e < 4; e++) acc[i][j][e] = 0.f;

    const int NC = K / KCH;

    // ---- stage chunk 0 into buffer 0 ----
    {
        char* bp = smem;
#pragma unroll
        for (int i = 0; i < 4; i++) {
            int f = i * NTHR + tid;
            int row = f >> 4, c4 = (f & 15) << 2;
            float4 v = *(const float4*)(A + (size_t)(bm + row) * K + c4);
            cvt_split_storeA(v, bp, bp + TILE_B, row, c4);
        }
#pragma unroll
        for (int i = 0; i < 4; i++) {
            int f = i * NTHR + tid;
            int row = f >> 4, c4 = (f & 15) << 2;
            float4 v = *(const float4*)(B + (size_t)(bn + row) * K + c4);
            cvt_storeB(v, bp + 2 * TILE_B, row, c4);
        }
    }
    __syncthreads();

    for (int c = 0; c < NC; ++c) {
        // ---- prefetch chunk c+1 into other buffer ----
        if (c + 1 < NC) {
            char* bp = smem + ((c + 1) & 1) * BUF_B;
            const int kb = (c + 1) * KCH;
#pragma unroll
            for (int i = 0; i < 4; i++) {
                int f = i * NTHR + tid;
                int row = f >> 4, c4 = (f & 15) << 2;
                float4 v = *(const float4*)(A + (size_t)(bm + row) * K + kb + c4);
                cvt_split_storeA(v, bp, bp + TILE_B, row, c4);
            }
#pragma unroll
            for (int i = 0; i < 4; i++) {
                int f = i * NTHR + tid;
                int row = f >> 4, c4 = (f & 15) << 2;
                float4 v = *(const float4*)(B + (size_t)(bn + row) * K + kb + c4);
                cvt_storeB(v, bp + 2 * TILE_B, row, c4);
            }
        }

        // ---- compute chunk c ----
        const uint32_t bufb = sb + (c & 1) * BUF_B;
        const uint32_t aHi = bufb, aLo = bufb + TILE_B, bHi = bufb + 2 * TILE_B;

#pragma unroll
        for (int ks = 0; ks < 4; ks++) {
            const uint32_t kso = (uint32_t)ks * 32u;
            uint32_t bh[4][2];
#pragma unroll
            for (int nt = 0; nt < 4; nt++) {
                const uint32_t ro = (uint32_t)(wn + nt * 8) * ASTR + kso + bro;
                ldmat_x2(bh[nt], bHi + ro);
            }
            uint32_t ah[2][4], al[2][4];
#pragma unroll
            for (int mt = 0; mt < 2; mt++) {
                const uint32_t ro = (uint32_t)(wm + mt * 16) * ASTR + kso + aro;
                ldmat_x4(ah[mt], aHi + ro);
                ldmat_x4(al[mt], aLo + ro);
            }
#pragma unroll
            for (int mt = 0; mt < 2; mt++)
#pragma unroll
                for (int nt = 0; nt < 4; nt++) {
                    mma_f16(acc[mt][nt], ah[mt], bh[nt]);
                    mma_f16(acc[mt][nt], al[mt], bh[nt]);
                }
        }
        __syncthreads();
    }

    // ---- epilogue from register fragments ----
    const int g   = lane >> 2;
    const int tig = lane & 3;
#pragma unroll
    for (int mt = 0; mt < 2; mt++) {
#pragma unroll
        for (int half = 0; half < 2; half++) {
            const int m = bm + wm + mt * 16 + g + 8 * half;
            float* crow = Cmat + (size_t)m * N;
            const float* rrow = (EPI == 1) ? (res + (size_t)m * N) : nullptr;
#pragma unroll
            for (int nt = 0; nt < 4; nt++) {
                const int cb = bn + wn + nt * 8 + 2 * tig;
                float v0 = acc[mt][nt][2 * half];
                float v1 = acc[mt][nt][2 * half + 1];
                if (EPI == 1) {
                    float2 rv = *(const float2*)(rrow + cb);
                    v0 += bias[cb] + rv.x;
                    v1 += bias[cb + 1] + rv.y;
                } else if (EPI == 2) {
                    float t0 = v0 + bias[cb], t1 = v1 + bias[cb + 1];
                    v0 = 0.5f * t0 * (1.0f + erff(t0 * 0.70710678118654752f));
                    v1 = 0.5f * t1 * (1.0f + erff(t1 * 0.70710678118654752f));
                }
                float2 ov = { v0, v1 };
                *(float2*)(crow + cb) = ov;
            }
        }
    }
}

// ---------------- LayerNorm: one warp per token ----------------
__global__ void ln_kernel(const float* __restrict__ x, const float* __restrict__ g,
                          const float* __restrict__ b, float* __restrict__ out) {
    const int warp = (blockIdx.x * 256 + threadIdx.x) >> 5;
    const int lane = threadIdx.x & 31;
    const float4* row = (const float4*)(x + (size_t)warp * CC);
    float4 v[4];
    float s = 0.f, q = 0.f;
#pragma unroll
    for (int i = 0; i < 4; i++) {
        v[i] = row[lane + 32 * i];
        s += v[i].x + v[i].y + v[i].z + v[i].w;
        q += v[i].x * v[i].x + v[i].y * v[i].y + v[i].z * v[i].z + v[i].w * v[i].w;
    }
#pragma unroll
    for (int o = 16; o; o >>= 1) {
        s += __shfl_xor_sync(0xFFFFFFFFu, s, o);
        q += __shfl_xor_sync(0xFFFFFFFFu, q, o);
    }
    const float mu  = s * (1.0f / CC);
    const float var = fmaxf(q * (1.0f / CC) - mu * mu, 0.0f);
    const float r   = rsqrtf(var + 1e-5f);

    float4* orow = (float4*)(out + (size_t)warp * CC);
    const float4* gg = (const float4*)g;
    const float4* bb = (const float4*)b;
#pragma unroll
    for (int i = 0; i < 4; i++) {
        float4 gv = gg[lane + 32 * i], bv = bb[lane + 32 * i], ov;
        ov.x = (v[i].x - mu) * r * gv.x + bv.x;
        ov.y = (v[i].y - mu) * r * gv.y + bv.y;
        ov.z = (v[i].z - mu) * r * gv.z + bv.z;
        ov.w = (v[i].w - mu) * r * gv.w + bv.w;
        orow[lane + 32 * i] = ov;
    }
}

// ---------------- Attention: one block per (seq, head), online softmax ------
__global__ void __launch_bounds__(256, 1)
attn_kernel(const float* __restrict__ qkv, float* __restrict__ o) {
    __shared__ float Ks[64 * 64];
    __shared__ float Vs[64 * 64];
    const int head = blockIdx.x;
    const int seqb = blockIdx.y * SEQ;
    const int tid  = threadIdx.x;
    const int tq   = seqb + tid;

    u64 q2[32], o2[32];
    {
        const float4* qp = (const float4*)(qkv + (size_t)tq * C3 + head * HDIM);
#pragma unroll
        for (int t = 0; t < 16; t++) {
            float4 v = qp[t];
            q2[2 * t]     = pack2(v.x * 0.125f, v.y * 0.125f);
            q2[2 * t + 1] = pack2(v.z * 0.125f, v.w * 0.125f);
            o2[2 * t] = 0ull; o2[2 * t + 1] = 0ull;
        }
    }
    float mx = -1e30f, sm = 0.f;

    for (int ck = 0; ck < 4; ++ck) {
        __syncthreads();
#pragma unroll
        for (int it = 0; it < 4; ++it) {
            const int idx = it * 256 + tid;
            const int r = idx >> 4, c4 = idx & 15;
            const float* base = qkv + (size_t)(seqb + ck * 64 + r) * C3 + head * HDIM + c4 * 4;
            ((float4*)Ks)[idx] = *(const float4*)(base + 512);
            ((float4*)Vs)[idx] = *(const float4*)(base + 1024);
        }
        __syncthreads();

        for (int m = 0; m < 64; m++) {
            const u64* K2 = (const u64*)(Ks + m * 64);
            u64 s4[4] = { 0ull, 0ull, 0ull, 0ull };
#pragma unroll
            for (int j = 0; j < 32; j += 4) {
                s4[0] = fma2(q2[j + 0], K2[j + 0], s4[0]);
                s4[1] = fma2(q2[j + 1], K2[j + 1], s4[1]);
                s4[2] = fma2(q2[j + 2], K2[j + 2], s4[2]);
                s4[3] = fma2(q2[j + 3], K2[j + 3], s4[3]);
            }
            float2 p0 = unpack2(s4[0]), p1 = unpack2(s4[1]);
            float2 p2 = unpack2(s4[2]), p3 = unpack2(s4[3]);
            const float s = ((p0.x + p0.y) + (p1.x + p1.y)) + ((p2.x + p2.y) + (p3.x + p3.y));

            const float mn   = fmaxf(mx, s);
            const float corr = __expf(mx - mn);
            const float p    = __expf(s - mn);
            sm = sm * corr + p;
            mx = mn;

            const u64 cd = pack2(corr, corr);
            const u64 pd = pack2(p, p);
            const u64* V2 = (const u64*)(Vs + m * 64);
#pragma unroll
            for (int j = 0; j < 32; j++)
                o2[j] = fma2(o2[j], cd, mul2(pd, V2[j]));
        }
    }

    const float inv = 1.0f / sm;
    float4* op = (float4*)(o + (size_t)tq * CC + head * HDIM);
#pragma unroll
    for (int t = 0; t < 16; t++) {
        float2 a = unpack2(o2[2 * t]);
        float2 b = unpack2(o2[2 * t + 1]);
        float4 v = { a.x * inv, a.y * inv, b.x * inv, b.y * inv };
        op[t] = v;
    }
}

// ---------------- launcher ----------------
extern "C" void kernel_launch(void* const* d_in, const int* in_sizes, int n_in,
                              void* d_out, int out_size) {
    const float* x     = (const float*)d_in[0];
    const float* ln1g  = (const float*)d_in[1];
    const float* ln1b  = (const float*)d_in[2];
    const float* wqkv  = (const float*)d_in[3];
    const float* wproj = (const float*)d_in[4];
    const float* bproj = (const float*)d_in[5];
    const float* ln2g  = (const float*)d_in[6];
    const float* ln2b  = (const float*)d_in[7];
    const float* w1    = (const float*)d_in[8];
    const float* b1    = (const float*)d_in[9];
    const float* w2    = (const float*)d_in[10];
    const float* b2    = (const float*)d_in[11];
    float* out = (float*)d_out;

    float *h1, *qkv, *o, *x1, *h2, *ff;
    cudaGetSymbolAddress((void**)&h1,  g_h1);
    cudaGetSymbolAddress((void**)&qkv, g_qkv);
    cudaGetSymbolAddress((void**)&o,   g_o);
    cudaGetSymbolAddress((void**)&x1,  g_x1);
    cudaGetSymbolAddress((void**)&h2,  g_h2);
    cudaGetSymbolAddress((void**)&ff,  g_ff);

    cudaFuncSetAttribute(gemm_mma<0>, cudaFuncAttributeMaxDynamicSharedMemorySize, GEMM_SMEM);
    cudaFuncSetAttribute(gemm_mma<1>, cudaFuncAttributeMaxDynamicSharedMemorySize, GEMM_SMEM);
    cudaFuncSetAttribute(gemm_mma<2>, cudaFuncAttributeMaxDynamicSharedMemorySize, GEMM_SMEM);

    // 1) LN1
    ln_kernel<<<TT / 8, 256>>>(x, ln1g, ln1b, h1);
    // 2) QKV = h1 @ w_qkv^T
    gemm_mma<0><<<dim3(C3 / 128, TT / 128), NTHR, GEMM_SMEM>>>(h1, wqkv, qkv, nullptr, nullptr, TT, C3, CC);
    // 3) attention
    attn_kernel<<<dim3(NHEAD, NSEQ), 256>>>(qkv, o);
    // 4) x1 = x + o @ w_proj^T + b_proj
    gemm_mma<1><<<dim3(CC / 128, TT / 128), NTHR, GEMM_SMEM>>>(o, wproj, x1, bproj, x, TT, CC, CC);
    // 5) LN2
    ln_kernel<<<TT / 8, 256>>>(x1, ln2g, ln2b, h2);
    // 6) ff = gelu(h2 @ w1^T + b1)
    gemm_mma<2><<<dim3(HID / 128, TT / 128), NTHR, GEMM_SMEM>>>(h2, w1, ff, b1, nullptr, TT, HID, CC);
    // 7) out = x1 + ff @ w2^T + b2
    gemm_mma<1><<<dim3(CC / 128, TT / 128), NTHR, GEMM_SMEM>>>(ff, w2, out, b2, x1, TT, CC, HID);
}